// round 14
// baseline (speedup 1.0000x reference)
#include <cuda_runtime.h>
#include <cuda_fp16.h>
#include <mma.h>
#include <cstdint>
#include <cstddef>

using namespace nvcuda;

// ============================================================================
// Problem: hidden [B,2048] f32, labels [B,28] i64/i32, W [280,2048] f32,
// bias [280] f32.  logits = hidden @ W^T + bias;  loss = mean NLL / 28.
// fp16 HMMA lane. hidden AND W pre-converted to fp16 (one streaming pass);
// GEMM hot loop = cp.async + LDSM + HMMA only, one barrier per chunk.
// CRITICAL ordering: CP_WAIT -> __syncthreads -> consume (cp.async completion
// is per-thread; the barrier is what publishes other threads' copies).
// ============================================================================
static constexpr int KDIM = 2048;
static constexpr int BATCH_MAX = 32768;
static constexpr int NTOT = 280;
static constexpr int NPAD = 288;        // 18 * 16
static constexpr int BM   = 128;
static constexpr int BK   = 32;         // K per chunk
static constexpr int NCH  = KDIM / BK;  // 64
static constexpr int THREADS = 384;     // 12 warps: 2 (m) x 6 (n)
static constexpr int STAGES = 4;

static constexpr int LDH = 40;          // fp16 rows: 32 halves + 8 pad (80B)
static constexpr int LDC = 292;         // f32 C rows

// SMEM layout (bytes)
static constexpr int SM_BIAS   = 0;                          // 288 f32
static constexpr int SM_STG    = 1280;
static constexpr int A_SZ      = BM * LDH * 2;               // 10240
static constexpr int B_SZ      = NPAD * LDH * 2;             // 23040
static constexpr int STAGE_SZ  = A_SZ + B_SZ;                // 33280
static constexpr int SM_STG_END= SM_STG + STAGES * STAGE_SZ; // 134400
static constexpr int SM_C      = SM_STG;                     // epilogue reuse
static constexpr int SM_EPI    = SM_STG + BM * LDC * 4;      // 150784
static constexpr int SM_TOTAL  = (SM_STG_END > SM_EPI) ? SM_STG_END : SM_EPI;

__device__ __forceinline__ uint32_t smem_u32(const void* p) {
    uint32_t a;
    asm("{ .reg .u64 t; cvta.to.shared.u64 t, %1; cvt.u32.u64 %0, t; }"
        : "=r"(a) : "l"(p));
    return a;
}

#define CP_ASYNC16(dst, src) \
    asm volatile("cp.async.cg.shared.global [%0], [%1], 16;" \
                 :: "r"(dst), "l"(src))
#define CP_COMMIT() asm volatile("cp.async.commit_group;" ::: "memory")
#define CP_WAIT(n)  asm volatile("cp.async.wait_group %0;" :: "n"(n) : "memory")

// ============================================================================
// Device scratch (16B-aligned for cp.async sources)
// ============================================================================
__device__ __align__(16) __half g_hhalf[(size_t)BATCH_MAX * KDIM]; // fp16 hidden
__device__ __align__(16) __half g_whalf[NPAD * KDIM];              // fp16 W, padded
__device__ float  g_logits_scratch[(size_t)BATCH_MAX * NTOT];
__device__ float  g_loss_scratch[1];
__device__ int    g_lab64;

// ============================================================================
// Prep 1: hidden f32 -> fp16 (pure streaming, float4 -> 4x half2)
// ============================================================================
__global__ void __launch_bounds__(256)
prep_hidden_kernel(const float4* __restrict__ h4, int n4) {
    int idx = blockIdx.x * 256 + threadIdx.x;
    if (idx < n4) {
        float4 f = h4[idx];
        __half2 a = __floats2half2_rn(f.x, f.y);
        __half2 b = __floats2half2_rn(f.z, f.w);
        reinterpret_cast<__half2*>(g_hhalf)[idx * 2 + 0] = a;
        reinterpret_cast<__half2*>(g_hhalf)[idx * 2 + 1] = b;
    }
}

// ============================================================================
// Prep 2: W -> g_whalf (fp16 RN, rows >= 280 zero). Label dtype detect.
// ============================================================================
__global__ void prep_w_kernel(const float* __restrict__ W,
                              const int* __restrict__ lab) {
    int idx = blockIdx.x * blockDim.x + threadIdx.x;
    if (idx < NPAD * KDIM) {
        int r = idx >> 11;   // / 2048
        g_whalf[idx] = (r < NTOT) ? __float2half_rn(W[idx]) : __half(0.f);
    }
    if (idx == 0) {
        int odd_or = 0;
        #pragma unroll 8
        for (int i = 0; i < 64; i++) odd_or |= lab[2 * i + 1];
        g_lab64 = (odd_or == 0) ? 1 : 0;
    }
}

// ============================================================================
// Fused GEMM (fp16 wmma m16n16k16, 4-stage cp.async) + bias + logits + loss
// Loop: wait(2) -> sync -> MMA(kc) -> issue(kc+3) -> commit.
// ============================================================================
__global__ void __launch_bounds__(THREADS, 1)
gemm_loss_kernel(const float* __restrict__ bias,
                 const int*   __restrict__ lab,
                 float* __restrict__ logits_arg,
                 float* __restrict__ loss_out,
                 int batch)
{
    extern __shared__ char smem[];
    float* sbias = reinterpret_cast<float*>(smem + SM_BIAS);
    float* logits = logits_arg ? logits_arg : g_logits_scratch;

    const uint32_t sbase = smem_u32(smem);
    const int tid = threadIdx.x;
    const int wid = tid >> 5;
    const int wm  = wid / 6;     // 0..1 -> 64-row slice
    const int wn  = wid % 6;     // 0..5 -> 48-col slice
    const int m0  = blockIdx.x * BM;

    for (int i = tid; i < NPAD; i += THREADS)
        sbias[i] = (i < NTOT) ? bias[i] : 0.f;

    wmma::fragment<wmma::accumulator, 16, 16, 16, float> c[4][3];
    #pragma unroll
    for (int i = 0; i < 4; i++)
        #pragma unroll
        for (int j = 0; j < 3; j++)
            wmma::fill_fragment(c[i][j], 0.f);

    // Per-thread incremental source pointers (advance 32 halves per chunk).
    // A: 512 x 16B ops; B: 1152 x 16B ops (3 rounds of 384 threads).
    const int a_r0 = tid >> 2, a_v = (tid & 3) * 8;
    const int a_r1 = (tid + THREADS) >> 2;
    const __half* a_src0 = g_hhalf + (size_t)(m0 + a_r0) * KDIM + a_v;
    const __half* a_src1 = g_hhalf + (size_t)(m0 + a_r1) * KDIM + a_v;
    const __half* b_src[3];
    #pragma unroll
    for (int i = 0; i < 3; i++) {
        int idx = tid + i * THREADS;
        b_src[i] = g_whalf + (size_t)(idx >> 2) * KDIM + (idx & 3) * 8;
    }
    const uint32_t a_d0 = (uint32_t)(a_r0 * 80 + (tid & 3) * 16);
    const uint32_t a_d1 = (uint32_t)(a_r1 * 80 + (tid & 3) * 16);
    uint32_t b_d[3];
    #pragma unroll
    for (int i = 0; i < 3; i++) {
        int idx = tid + i * THREADS;
        b_d[i] = (uint32_t)((idx >> 2) * 80 + (idx & 3) * 16);
    }

    auto issue_stage = [&](int kc, int buf) {
        const uint32_t a_dst = sbase + SM_STG + buf * STAGE_SZ;
        const uint32_t b_dst = a_dst + A_SZ;
        const int koff = kc * BK;   // halves
        CP_ASYNC16(a_dst + a_d0, a_src0 + koff);
        if (tid + THREADS < 512)
            CP_ASYNC16(a_dst + a_d1, a_src1 + koff);
        #pragma unroll
        for (int i = 0; i < 3; i++)
            CP_ASYNC16(b_dst + b_d[i], b_src[i] + koff);
    };

    issue_stage(0, 0); CP_COMMIT();
    issue_stage(1, 1); CP_COMMIT();
    issue_stage(2, 2); CP_COMMIT();

    for (int kc = 0; kc < NCH; kc++) {
        // groups committed so far = stages 0..kc+2; leave newest 2 pending
        CP_WAIT(2);             // THIS thread's stage-kc copies complete
        __syncthreads();        // publish ALL threads' stage-kc copies;
                                // also: everyone done with compute kc-1,
                                // so buffer (kc-1)%4 == (kc+3)%4 is free

        const __half* As = reinterpret_cast<const __half*>(
            smem + SM_STG + (kc % STAGES) * STAGE_SZ);
        const __half* Bs = As + A_SZ / 2;

        #pragma unroll
        for (int ks = 0; ks < 2; ks++) {
            const int k0 = ks * 16;
            wmma::fragment<wmma::matrix_a, 16, 16, 16, __half,
                           wmma::row_major> a[4];
            wmma::fragment<wmma::matrix_b, 16, 16, 16, __half,
                           wmma::col_major> b[3];
            #pragma unroll
            for (int i = 0; i < 4; i++)
                wmma::load_matrix_sync(a[i], As + (wm * 64 + i * 16) * LDH + k0, LDH);
            #pragma unroll
            for (int j = 0; j < 3; j++)
                wmma::load_matrix_sync(b[j], Bs + (wn * 48 + j * 16) * LDH + k0, LDH);
            #pragma unroll
            for (int i = 0; i < 4; i++)
                #pragma unroll
                for (int j = 0; j < 3; j++)
                    wmma::mma_sync(c[i][j], a[i], b[j], c[i][j]);
        }

        // issue AFTER compute (R4-proven); target buffer freed by the barrier
        if (kc + 3 < NCH) issue_stage(kc + 3, (kc + 3) % STAGES);
        CP_COMMIT();            // uniform group count even when empty
    }
    __syncthreads();            // all warps done with stage smem

    // ---- epilogue: full 128x292 C in smem (one pass) ----
    float* Cs = reinterpret_cast<float*>(smem + SM_C);
    #pragma unroll
    for (int i = 0; i < 4; i++)
        #pragma unroll
        for (int j = 0; j < 3; j++)
            wmma::store_matrix_sync(
                Cs + (wm * 64 + i * 16) * LDC + wn * 48 + j * 16,
                c[i][j], LDC, wmma::mem_row_major);
    __syncthreads();

    // logits: float4 LDS (aligned) -> 4 scalar STG (gmem base may be 4B-aligned)
    for (int idx = tid; idx < BM * (NTOT / 4); idx += THREADS) {
        int r = idx / (NTOT / 4), n4 = idx - r * (NTOT / 4);
        float4 v  = *reinterpret_cast<const float4*>(Cs + r * LDC + n4 * 4);
        float4 bb = *reinterpret_cast<const float4*>(sbias + n4 * 4);
        float* dst = logits + (size_t)(m0 + r) * NTOT + n4 * 4;
        dst[0] = v.x + bb.x;
        dst[1] = v.y + bb.y;
        dst[2] = v.z + bb.z;
        dst[3] = v.w + bb.w;
    }

    // loss: 128 rows x 28 heads
    const int lab64 = g_lab64;
    float loss_part = 0.f;
    for (int t = tid; t < BM * 28; t += THREADS) {
        int r = t / 28, h = t - r * 28;
        const float* x  = Cs + r * LDC + h * 10;
        const float* bb = sbias + h * 10;
        float v[10], mx = -1e30f;
        #pragma unroll
        for (int i = 0; i < 10; i++) { v[i] = x[i] + bb[i]; mx = fmaxf(mx, v[i]); }
        float s = 0.f;
        #pragma unroll
        for (int i = 0; i < 10; i++) s += __expf(v[i] - mx);
        int li = (m0 + r) * 28 + h;
        int label = lab64 ? lab[2 * li] : lab[li];
        loss_part += mx + __logf(s) - v[label];
    }

    #pragma unroll
    for (int off = 16; off > 0; off >>= 1)
        loss_part += __shfl_xor_sync(0xFFFFFFFF, loss_part, off);
    __shared__ float warp_loss[12];
    if ((tid & 31) == 0) warp_loss[wid] = loss_part;
    __syncthreads();
    if (tid == 0) {
        float t = 0.f;
        #pragma unroll
        for (int i = 0; i < 12; i++) t += warp_loss[i];
        atomicAdd(loss_out, t * (1.0f / ((float)batch * 28.0f)));
    }
}

// ============================================================================
// kernel_launch
// ============================================================================
extern "C" void kernel_launch(void* const* d_in, const int* in_sizes, int n_in,
                              void* d_out, int out_size)
{
    const float* hidden = (const float*)d_in[0];
    const int*   labels = (const int*)d_in[1];
    const float* W      = (const float*)d_in[2];
    const float* bias   = (const float*)d_in[3];

    const int batch = in_sizes[0] / KDIM;                  // 32768
    const long long LOGN = (long long)batch * NTOT;

    float* out = (float*)d_out;
    float* loss_ptr = nullptr;
    float* logits_ptr = nullptr;
    if ((long long)out_size >= LOGN + 1) {
        loss_ptr = out;
        logits_ptr = out + 1;
    } else if ((long long)out_size == LOGN) {
        logits_ptr = out;
    } else {
        loss_ptr = out;
    }
    if (!loss_ptr) {
        void* p = nullptr;
        cudaGetSymbolAddress(&p, g_loss_scratch);
        loss_ptr = (float*)p;
    }

    static bool attr_done = false;
    if (!attr_done) {
        cudaFuncSetAttribute(gemm_loss_kernel,
                             cudaFuncAttributeMaxDynamicSharedMemorySize, SM_TOTAL);
        attr_done = true;
    }

    const int n4 = batch * KDIM / 4;   // float4 count
    prep_hidden_kernel<<<(n4 + 255) / 256, 256>>>(
        reinterpret_cast<const float4*>(hidden), n4);
    prep_w_kernel<<<(NPAD * KDIM + 255) / 256, 256>>>(W, labels);
    cudaMemsetAsync(loss_ptr, 0, sizeof(float));
    gemm_loss_kernel<<<batch / BM, THREADS, SM_TOTAL>>>(
        bias, labels, logits_ptr, loss_ptr, batch);
}

// round 15
// speedup vs baseline: 1.2836x; 1.2836x over previous
#include <cuda_runtime.h>
#include <cuda_fp16.h>
#include <mma.h>
#include <cstdint>
#include <cstddef>

using namespace nvcuda;

// ============================================================================
// Problem: hidden [B,2048] f32, labels [B,28] i64/i32, W [280,2048] f32,
// bias [280] f32.  logits = hidden @ W^T + bias;  loss = mean NLL / 28.
// fp16 HMMA lane. A staged as RAW f32 via cp.async and converted to fp16 by
// the SAME thread that copied it (own cp.async data is visible after
// wait_group without a barrier). One __syncthreads per chunk; convert runs
// AFTER the MMAs so its latency hides under tensor-pipe drain.
// ============================================================================
static constexpr int KDIM = 2048;
static constexpr int BATCH_MAX = 32768;
static constexpr int NTOT = 280;
static constexpr int NPAD = 288;        // 18 * 16
static constexpr int BM   = 128;
static constexpr int BK   = 32;         // K per chunk
static constexpr int NCH  = KDIM / BK;  // 64
static constexpr int THREADS = 384;     // 12 warps: 2 (m) x 6 (n)
static constexpr int STAGES = 4;

static constexpr int LDA_RAW = 36;      // raw A row: 32 f32 + 4 pad (144B)
static constexpr int LDH     = 40;      // fp16 rows: 32 halves + 8 pad (80B)
static constexpr int LDC     = 292;     // f32 C rows

// SMEM layout (bytes)
static constexpr int SM_BIAS   = 0;                          // 288 f32
static constexpr int SM_STG    = 1280;
static constexpr int A_RAW_SZ  = BM * LDA_RAW * 4;           // 18432
static constexpr int B_SZ      = NPAD * LDH * 2;             // 23040
static constexpr int STAGE_SZ  = A_RAW_SZ + B_SZ;            // 41472
static constexpr int SM_AH     = SM_STG + STAGES * STAGE_SZ; // 167168
static constexpr int AH_SZ     = BM * LDH * 2;               // 10240 (x2)
static constexpr int SM_C      = SM_STG;                     // epilogue reuse
static constexpr int SM_EPI    = SM_STG + BM * LDC * 4;      // 150784
static constexpr int SM_AH_END = SM_AH + 2 * AH_SZ;          // 187648
static constexpr int SM_TOTAL  = (SM_AH_END > SM_EPI) ? SM_AH_END : SM_EPI;

__device__ __forceinline__ uint32_t smem_u32(const void* p) {
    uint32_t a;
    asm("{ .reg .u64 t; cvta.to.shared.u64 t, %1; cvt.u32.u64 %0, t; }"
        : "=r"(a) : "l"(p));
    return a;
}

#define CP_ASYNC16(dst, src) \
    asm volatile("cp.async.cg.shared.global [%0], [%1], 16;" \
                 :: "r"(dst), "l"(src))
#define CP_COMMIT() asm volatile("cp.async.commit_group;" ::: "memory")
#define CP_WAIT(n)  asm volatile("cp.async.wait_group %0;" :: "n"(n) : "memory")

// ============================================================================
// Device scratch
// ============================================================================
__device__ __align__(16) __half g_whalf[NPAD * KDIM];   // fp16 W, zero-padded
__device__ float  g_logits_scratch[(size_t)BATCH_MAX * NTOT];
__device__ float  g_loss_scratch[1];
__device__ int    g_lab64;

// ============================================================================
// Prep: W -> g_whalf (fp16 RN, rows >= 280 zero). Label dtype detect.
// ============================================================================
__global__ void prep_w_kernel(const float* __restrict__ W,
                              const int* __restrict__ lab) {
    int idx = blockIdx.x * blockDim.x + threadIdx.x;
    if (idx < NPAD * KDIM) {
        int r = idx >> 11;   // / 2048
        g_whalf[idx] = (r < NTOT) ? __float2half_rn(W[idx]) : __half(0.f);
    }
    if (idx == 0) {
        int odd_or = 0;
        #pragma unroll 8
        for (int i = 0; i < 64; i++) odd_or |= lab[2 * i + 1];
        g_lab64 = (odd_or == 0) ? 1 : 0;
    }
}

// ============================================================================
// Fused GEMM (fp16 wmma m16n16k16, 4-stage cp.async) + bias + logits + loss
// Loop: sync -> MMA(kc) -> issue(kc+3) -> commit -> wait(2) -> convert(kc+1).
// ============================================================================
__global__ void __launch_bounds__(THREADS, 1)
gemm_loss_kernel(const float* __restrict__ hidden,
                 const float* __restrict__ bias,
                 const int*   __restrict__ lab,
                 float* __restrict__ logits_arg,
                 float* __restrict__ loss_out,
                 int batch)
{
    extern __shared__ char smem[];
    float* sbias = reinterpret_cast<float*>(smem + SM_BIAS);
    float* logits = logits_arg ? logits_arg : g_logits_scratch;

    const uint32_t sbase = smem_u32(smem);
    const int tid = threadIdx.x;
    const int wid = tid >> 5;
    const int wm  = wid / 6;     // 0..1 -> 64-row slice
    const int wn  = wid % 6;     // 0..5 -> 48-col slice
    const int m0  = blockIdx.x * BM;

    for (int i = tid; i < NPAD; i += THREADS)
        sbias[i] = (i < NTOT) ? bias[i] : 0.f;

    wmma::fragment<wmma::accumulator, 16, 16, 16, float> c[4][3];
    #pragma unroll
    for (int i = 0; i < 4; i++)
        #pragma unroll
        for (int j = 0; j < 3; j++)
            wmma::fill_fragment(c[i][j], 0.f);

    // ---- cp.async stage: raw f32 A 128x32 (+pad), fp16 B 288x32 (+pad) ----
    // A: 1024 x 16B pieces (128 rows x 8 float4); thread owns idx = tid + i*384.
    // B: 1152 x 16B pieces (288 rows x 4), pre-converted fp16.
    auto issue_stage = [&](int kc, int buf) {
        const uint32_t a_dst = sbase + SM_STG + buf * STAGE_SZ;
        const uint32_t b_dst = a_dst + A_RAW_SZ;
        const int k0 = kc * BK;
        #pragma unroll
        for (int i = 0; i < 3; i++) {
            int idx = tid + i * THREADS;
            if (idx < 1024) {
                int r = idx >> 3, v = idx & 7;
                const float* src = hidden + (size_t)(m0 + r) * KDIM + k0 + v * 4;
                CP_ASYNC16(a_dst + (uint32_t)(r * 144 + v * 16), src);
            }
        }
        #pragma unroll
        for (int i = 0; i < 3; i++) {
            int idx = tid + i * THREADS;
            const __half* src = g_whalf + (size_t)(idx >> 2) * KDIM + (idx & 3) * 8 + k0;
            CP_ASYNC16(b_dst + (uint32_t)((idx >> 2) * 80 + (idx & 3) * 16), src);
        }
    };

    // Convert THIS thread's own A pieces of stage `buf` -> fp16 dst_ah.
    // Safe without a barrier: own cp.async data is visible after wait_group.
    auto convert_a = [&](int buf, __half* dst_ah) {
        const char* stg = smem + SM_STG + buf * STAGE_SZ;
        #pragma unroll
        for (int i = 0; i < 3; i++) {
            int idx = tid + i * THREADS;
            if (idx < 1024) {
                int r = idx >> 3, v = idx & 7;
                float4 f = *reinterpret_cast<const float4*>(stg + r * 144 + v * 16);
                __half2 h0 = __floats2half2_rn(f.x, f.y);
                __half2 h1 = __floats2half2_rn(f.z, f.w);
                uint2 u = make_uint2(*reinterpret_cast<uint32_t*>(&h0),
                                     *reinterpret_cast<uint32_t*>(&h1));
                *reinterpret_cast<uint2*>(dst_ah + r * LDH + v * 4) = u;
            }
        }
    };

    __half* ah0 = reinterpret_cast<__half*>(smem + SM_AH);
    __half* ah1 = reinterpret_cast<__half*>(smem + SM_AH + AH_SZ);

    // prologue: fill 3 stages; convert chunk 0 (own pieces, no barrier)
    issue_stage(0, 0); CP_COMMIT();
    issue_stage(1, 1); CP_COMMIT();
    issue_stage(2, 2); CP_COMMIT();
    CP_WAIT(2);                 // own stage-0 copies complete
    convert_a(0, ah0);

    for (int kc = 0; kc < NCH; kc++) {
        __syncthreads();        // publishes: stage kc (B, all threads' copies,
                                // each owner waited last iter) + ah[kc&1]

        // MMA chunk kc: A from ah[kc&1], B from stage kc%4
        const __half* ah = (kc & 1) ? ah1 : ah0;
        const __half* Bs = reinterpret_cast<const __half*>(
            smem + SM_STG + (kc % STAGES) * STAGE_SZ + A_RAW_SZ);

        #pragma unroll
        for (int ks = 0; ks < 2; ks++) {
            const int k0 = ks * 16;
            wmma::fragment<wmma::matrix_a, 16, 16, 16, __half,
                           wmma::row_major> a[4];
            wmma::fragment<wmma::matrix_b, 16, 16, 16, __half,
                           wmma::col_major> b[3];
            #pragma unroll
            for (int i = 0; i < 4; i++)
                wmma::load_matrix_sync(a[i], ah + (wm * 64 + i * 16) * LDH + k0, LDH);
            #pragma unroll
            for (int j = 0; j < 3; j++)
                wmma::load_matrix_sync(b[j], Bs + (wn * 48 + j * 16) * LDH + k0, LDH);
            #pragma unroll
            for (int i = 0; i < 4; i++)
                #pragma unroll
                for (int j = 0; j < 3; j++)
                    wmma::mma_sync(c[i][j], a[i], b[j], c[i][j]);
        }

        // prefetch stage kc+3 into buf (kc-1)%4 (readers were pre-barrier)
        if (kc + 3 < NCH) issue_stage(kc + 3, (kc + 3) % STAGES);
        CP_COMMIT();            // uniform group count even when empty

        // own stage-(kc+1) copies complete (kc+2, kc+3 may remain in flight)
        CP_WAIT(2);

        // convert NEXT chunk's A (own pieces) -> other ah buffer;
        // runs while this chunk's HMMAs drain the tensor pipe
        if (kc + 1 < NCH)
            convert_a((kc + 1) % STAGES, (kc & 1) ? ah0 : ah1);
    }
    __syncthreads();            // all warps done with stage smem

    // ---- epilogue: full 128x292 C in smem (one pass) ----
    float* Cs = reinterpret_cast<float*>(smem + SM_C);
    #pragma unroll
    for (int i = 0; i < 4; i++)
        #pragma unroll
        for (int j = 0; j < 3; j++)
            wmma::store_matrix_sync(
                Cs + (wm * 64 + i * 16) * LDC + wn * 48 + j * 16,
                c[i][j], LDC, wmma::mem_row_major);
    __syncthreads();

    // logits: float4 LDS (aligned) -> 4 scalar STG (gmem base may be 4B-aligned)
    for (int idx = tid; idx < BM * (NTOT / 4); idx += THREADS) {
        int r = idx / (NTOT / 4), n4 = idx - r * (NTOT / 4);
        float4 v  = *reinterpret_cast<const float4*>(Cs + r * LDC + n4 * 4);
        float4 bb = *reinterpret_cast<const float4*>(sbias + n4 * 4);
        float* dst = logits + (size_t)(m0 + r) * NTOT + n4 * 4;
        dst[0] = v.x + bb.x;
        dst[1] = v.y + bb.y;
        dst[2] = v.z + bb.z;
        dst[3] = v.w + bb.w;
    }

    // loss: 128 rows x 28 heads
    const int lab64 = g_lab64;
    float loss_part = 0.f;
    for (int t = tid; t < BM * 28; t += THREADS) {
        int r = t / 28, h = t - r * 28;
        const float* x  = Cs + r * LDC + h * 10;
        const float* bb = sbias + h * 10;
        float v[10], mx = -1e30f;
        #pragma unroll
        for (int i = 0; i < 10; i++) { v[i] = x[i] + bb[i]; mx = fmaxf(mx, v[i]); }
        float s = 0.f;
        #pragma unroll
        for (int i = 0; i < 10; i++) s += __expf(v[i] - mx);
        int li = (m0 + r) * 28 + h;
        int label = lab64 ? lab[2 * li] : lab[li];
        loss_part += mx + __logf(s) - v[label];
    }

    #pragma unroll
    for (int off = 16; off > 0; off >>= 1)
        loss_part += __shfl_xor_sync(0xFFFFFFFF, loss_part, off);
    __shared__ float warp_loss[12];
    if ((tid & 31) == 0) warp_loss[wid] = loss_part;
    __syncthreads();
    if (tid == 0) {
        float t = 0.f;
        #pragma unroll
        for (int i = 0; i < 12; i++) t += warp_loss[i];
        atomicAdd(loss_out, t * (1.0f / ((float)batch * 28.0f)));
    }
}

// ============================================================================
// kernel_launch
// ============================================================================
extern "C" void kernel_launch(void* const* d_in, const int* in_sizes, int n_in,
                              void* d_out, int out_size)
{
    const float* hidden = (const float*)d_in[0];
    const int*   labels = (const int*)d_in[1];
    const float* W      = (const float*)d_in[2];
    const float* bias   = (const float*)d_in[3];

    const int batch = in_sizes[0] / KDIM;                  // 32768
    const long long LOGN = (long long)batch * NTOT;

    float* out = (float*)d_out;
    float* loss_ptr = nullptr;
    float* logits_ptr = nullptr;
    if ((long long)out_size >= LOGN + 1) {
        loss_ptr = out;
        logits_ptr = out + 1;
    } else if ((long long)out_size == LOGN) {
        logits_ptr = out;
    } else {
        loss_ptr = out;
    }
    if (!loss_ptr) {
        void* p = nullptr;
        cudaGetSymbolAddress(&p, g_loss_scratch);
        loss_ptr = (float*)p;
    }

    static bool attr_done = false;
    if (!attr_done) {
        cudaFuncSetAttribute(gemm_loss_kernel,
                             cudaFuncAttributeMaxDynamicSharedMemorySize, SM_TOTAL);
        attr_done = true;
    }

    prep_w_kernel<<<(NPAD * KDIM + 255) / 256, 256>>>(W, labels);
    cudaMemsetAsync(loss_ptr, 0, sizeof(float));
    gemm_loss_kernel<<<batch / BM, THREADS, SM_TOTAL>>>(
        hidden, bias, labels, logits_ptr, loss_ptr, batch);
}